// round 4
// baseline (speedup 1.0000x reference)
#include <cuda_runtime.h>

#define N_NODES 100000
#define N_EDGES 3200000
#define D_FEAT  256
#define D_HID   30
#define HPAD    32          // h row padded to 128B so each gather is one L2 line
#define SCAN_BLOCKS 98      // ceil(100000/1024)

// ---------------- scratch (device globals; zero-initialized at load) --------
__device__ float g_h[N_NODES * HPAD];     // 12.8 MB transformed features
__device__ float g_dis[N_NODES];          // rsqrt(deg)
__device__ float g_z[N_NODES];            // per-node scalar after layer-2 transform
__device__ int   g_cnt[N_NODES];          // in-degree histogram (real edges only)
__device__ int   g_rowptr[N_NODES + 1];   // CSR row pointers (by target col)
__device__ int   g_cursor[N_NODES];       // scatter cursors
__device__ int2  g_entries[N_EDGES];      // (src_row, bits(dis[src]))
__device__ int   g_bsums[128];            // scan block sums

// ---------------- init: zero the histogram every call -----------------------
__global__ void k_init() {
    int i = blockIdx.x * 256 + threadIdx.x;
    if (i < N_NODES) g_cnt[i] = 0;
}

// ---------------- histogram of target nodes (edge_index is int32 [2,E]) -----
__global__ void k_hist(const int* __restrict__ ei) {
    int e = blockIdx.x * 256 + threadIdx.x;
    if (e < N_EDGES) {
        int c = ei[N_EDGES + e];
        if ((unsigned)c < (unsigned)N_NODES) atomicAdd(&g_cnt[c], 1);
    }
}

// ---------------- block-level exclusive scan --------------------------------
__global__ void k_scan1() {
    __shared__ int s[1024];
    int t = threadIdx.x;
    int i = blockIdx.x * 1024 + t;
    int v = (i < N_NODES) ? g_cnt[i] : 0;
    s[t] = v;
    __syncthreads();
    #pragma unroll
    for (int off = 1; off < 1024; off <<= 1) {
        int add = (t >= off) ? s[t - off] : 0;
        __syncthreads();
        s[t] += add;
        __syncthreads();
    }
    if (i < N_NODES) g_rowptr[i] = s[t] - v;   // block-local exclusive
    if (t == 1023) g_bsums[blockIdx.x] = s[t];
}

__global__ void k_scan2() {
    if (threadIdx.x == 0) {
        int acc = 0;
        for (int b = 0; b < SCAN_BLOCKS; b++) {
            int v = g_bsums[b];
            g_bsums[b] = acc;
            acc += v;
        }
    }
}

__global__ void k_scan3() {
    int i = blockIdx.x * 256 + threadIdx.x;
    if (i < N_NODES) {
        int rp = g_rowptr[i] + g_bsums[i >> 10];
        g_rowptr[i] = rp;
        g_cursor[i] = rp;
        // deg includes the self-loop (+1); deg >= 1 always
        g_dis[i] = rsqrtf((float)(g_cnt[i] + 1));
    }
    if (i == 0) g_rowptr[N_NODES] = N_EDGES;
}

// ---------------- CSR scatter: pack (src, dis[src]) -------------------------
__global__ void k_scatter(const int* __restrict__ ei) {
    int e = blockIdx.x * 256 + threadIdx.x;
    if (e < N_EDGES) {
        int r = ei[e];
        int c = ei[N_EDGES + e];
        if ((unsigned)r < (unsigned)N_NODES && (unsigned)c < (unsigned)N_NODES) {
            float dr = g_dis[r];
            int pos = atomicAdd(&g_cursor[c], 1);
            g_entries[pos] = make_int2(r, __float_as_int(dr));
        }
    }
}

// ---------------- GEMM: h = x @ W1 (fp32 FFMA) ------------------------------
// 128 threads/block, 2 nodes/thread -> 256 nodes/block. W1 staged in smem
// padded to 32 floats/row for float4 LDS; x staged in 8-wide K chunks.
__global__ void __launch_bounds__(128) k_gemm(const float* __restrict__ x,
                                              const float* __restrict__ W1) {
    __shared__ __align__(16) float Ws[D_FEAT * 32];  // 32 KB
    __shared__ float xs[256 * 9];                    // 9 KB (pad 9 vs bank conflicts)
    int t  = threadIdx.x;
    int n0 = blockIdx.x * 256;

    #pragma unroll
    for (int i = 0; i < 60; i++) {                   // 60*128 = 7680 = 256*30
        int flat = t + i * 128;
        Ws[(flat / 30) * 32 + (flat % 30)] = W1[flat];
    }

    float accA[30], accB[30];
    #pragma unroll
    for (int j = 0; j < 30; j++) { accA[j] = 0.f; accB[j] = 0.f; }

    for (int kc = 0; kc < 32; kc++) {                // 32 chunks of 8
        __syncthreads();
        #pragma unroll
        for (int i = 0; i < 4; i++) {                // 512 float4 loads / 128 thr
            int flat4 = t + i * 128;
            int n = flat4 >> 1;
            int p = flat4 & 1;
            int gn = n0 + n;
            if (gn < N_NODES) {
                float4 v = *(const float4*)&x[gn * D_FEAT + kc * 8 + p * 4];
                float* xr = &xs[n * 9 + p * 4];
                xr[0] = v.x; xr[1] = v.y; xr[2] = v.z; xr[3] = v.w;
            }
        }
        __syncthreads();
        #pragma unroll
        for (int kk = 0; kk < 8; kk++) {
            float xa = xs[t * 9 + kk];
            float xb = xs[(t + 128) * 9 + kk];
            const float* wr = &Ws[(kc * 8 + kk) * 32];
            #pragma unroll
            for (int j4 = 0; j4 < 7; j4++) {
                float4 w = *(const float4*)&wr[j4 * 4];
                accA[j4*4+0] += xa * w.x;  accB[j4*4+0] += xb * w.x;
                accA[j4*4+1] += xa * w.y;  accB[j4*4+1] += xb * w.y;
                accA[j4*4+2] += xa * w.z;  accB[j4*4+2] += xb * w.z;
                accA[j4*4+3] += xa * w.w;  accB[j4*4+3] += xb * w.w;
            }
            float2 w2 = *(const float2*)&wr[28];
            accA[28] += xa * w2.x;  accB[28] += xb * w2.x;
            accA[29] += xa * w2.y;  accB[29] += xb * w2.y;
        }
    }

    int na = n0 + t, nb = n0 + 128 + t;
    if (na < N_NODES) {
        #pragma unroll
        for (int j = 0; j < 30; j++) g_h[na * HPAD + j] = accA[j];
    }
    if (nb < N_NODES) {
        #pragma unroll
        for (int j = 0; j < 30; j++) g_h[nb * HPAD + j] = accB[j];
    }
}

// ---------------- layer-1 aggregate + relu + (·W2) fused --------------------
// One warp per target node; lanes 0..29 own features. Self-loop added
// analytically. Epilogue computes z[c] = relu(agg + b1) . W2 (never stores h1).
__global__ void __launch_bounds__(256) k_agg1(const float* __restrict__ b1,
                                              const float* __restrict__ W2) {
    int c    = blockIdx.x * 8 + (threadIdx.x >> 5);
    int lane = threadIdx.x & 31;
    float dc = g_dis[c];
    int s = g_rowptr[c];
    int e = g_rowptr[c + 1];

    // self-loop: h[c] * dis[c]^2 (pad lanes read zeros)
    float acc  = g_h[c * HPAD + lane] * (dc * dc);
    float acc2 = 0.f;

    int i = s;
    for (; i + 1 < e; i += 2) {
        int2 a = g_entries[i];
        int2 b = g_entries[i + 1];
        acc  += g_h[a.x * HPAD + lane] * (__int_as_float(a.y) * dc);
        acc2 += g_h[b.x * HPAD + lane] * (__int_as_float(b.y) * dc);
    }
    if (i < e) {
        int2 a = g_entries[i];
        acc += g_h[a.x * HPAD + lane] * (__int_as_float(a.y) * dc);
    }
    acc += acc2;

    float p = 0.f;
    if (lane < D_HID) {
        float h1 = fmaxf(acc + b1[lane], 0.f);
        p = h1 * W2[lane];
    }
    #pragma unroll
    for (int off = 16; off > 0; off >>= 1)
        p += __shfl_down_sync(0xFFFFFFFFu, p, off);
    if (lane == 0) g_z[c] = p;
}

// ---------------- layer-2 scalar aggregate + sigmoid ------------------------
// One warp per node, lanes parallel over edges (z table is L2-resident 400KB).
__global__ void __launch_bounds__(256) k_agg2(const float* __restrict__ b2,
                                              float* __restrict__ out) {
    int c    = blockIdx.x * 8 + (threadIdx.x >> 5);
    int lane = threadIdx.x & 31;
    float dc = g_dis[c];
    int s = g_rowptr[c];
    int e = g_rowptr[c + 1];

    float acc = (lane == 0) ? g_z[c] * dc * dc : 0.f;   // self-loop
    for (int i = s + lane; i < e; i += 32) {
        int2 a = g_entries[i];
        acc += g_z[a.x] * (__int_as_float(a.y) * dc);
    }
    #pragma unroll
    for (int off = 16; off > 0; off >>= 1)
        acc += __shfl_down_sync(0xFFFFFFFFu, acc, off);
    if (lane == 0) {
        float v = acc + b2[0];
        out[c] = 1.f / (1.f + __expf(-v));
    }
}

// ---------------- launcher ---------------------------------------------------
extern "C" void kernel_launch(void* const* d_in, const int* in_sizes, int n_in,
                              void* d_out, int out_size) {
    const float* x  = (const float*)d_in[0];
    const int*   ei = (const int*)d_in[1];     // int64 in source -> int32 (JAX x64 disabled)
    const float* W1 = (const float*)d_in[2];
    const float* b1 = (const float*)d_in[3];
    const float* W2 = (const float*)d_in[4];
    const float* b2 = (const float*)d_in[5];
    float*       out = (float*)d_out;

    const int nodeBlocks = (N_NODES + 255) / 256;   // 391
    const int edgeBlocks = (N_EDGES + 255) / 256;   // 12500
    const int warpBlocks = N_NODES / 8;             // 12500 (exact)

    k_init   <<<nodeBlocks, 256>>>();
    k_hist   <<<edgeBlocks, 256>>>(ei);
    k_gemm   <<<nodeBlocks, 128>>>(x, W1);
    k_scan1  <<<SCAN_BLOCKS, 1024>>>();
    k_scan2  <<<1, 32>>>();
    k_scan3  <<<nodeBlocks, 256>>>();
    k_scatter<<<edgeBlocks, 256>>>(ei);
    k_agg1   <<<warpBlocks, 256>>>(b1, W2);
    k_agg2   <<<warpBlocks, 256>>>(b2, out);
}